// round 13
// baseline (speedup 1.0000x reference)
#include <cuda_runtime.h>
#include <cuda_fp16.h>
#include <cstdint>

#define MAXN 100352
#define MAXE 1703936
#define D_OUT 64
#define MAXNB 128

// ---------------- scratch ----------------
__device__ __half g_hh [(size_t)MAXN * D_OUT];   // fp16 layer-1 output
__device__ __half g_xlh[(size_t)MAXN * D_OUT];   // fp16 gather array
__device__ float  g_xr[(size_t)MAXN * D_OUT];
__device__ __half g_wt1[128 * 128];              // (W1l|W1r)^T fp16 [n][k]
__device__ __half g_wt2[128 * 64];               // (W2l|W2r)^T fp16 [n][k]
__device__ int    g_deg[MAXN];
__device__ int    g_rowptr[MAXN + 1];
__device__ int    g_srcs[MAXE];
__device__ int    g_off[MAXE];
__device__ int    g_flags[MAXNB];
__device__ int    g_aggv [MAXNB];
__device__ int    g_prefv[MAXNB];

// ---------------- W fp16 transpose ----------------
__global__ void k_wcvt(const float* __restrict__ W1l, const float* __restrict__ W1r,
                       const float* __restrict__ W2l, const float* __restrict__ W2r,
                       __half* __restrict__ wt1, __half* __restrict__ wt2) {
    int i = blockIdx.x * 256 + threadIdx.x;
    if (i < 128 * 128) {
        int nn = i >> 7, k = i & 127;
        float w = (nn < 64) ? W1l[k * 64 + nn] : W1r[k * 64 + (nn - 64)];
        wt1[i] = __float2half(w);
    }
    if (i < 128 * 64) {
        int nn = i >> 6, k = i & 63;
        float w = (nn < 64) ? W2l[k * 64 + nn] : W2r[k * 64 + (nn - 64)];
        wt2[i] = __float2half(w);
    }
}

__global__ void k_zerodeg(int* __restrict__ deg, int* __restrict__ flags,
                          int n, int nb) {
    int i = blockIdx.x * 256 + threadIdx.x;
    if (i < n) deg[i] = 0;
    if (i < nb) flags[i] = 0;
}

// ---------------- CSR build ----------------
__global__ void k_count(const int* __restrict__ ei, int* __restrict__ deg,
                        int* __restrict__ offb, int E, int ET) {
    int e = blockIdx.x * blockDim.x + threadIdx.x;
    if (e >= ET) return;
    int dst = (e < E) ? ei[E + e] : (e - E);
    offb[e] = atomicAdd(&deg[dst], 1);
}

__global__ void k_scan(const int* __restrict__ deg, int* __restrict__ rowptr,
                       int* __restrict__ flags,
                       int* __restrict__ aggv, int* __restrict__ prefv,
                       int n, int etot) {
    __shared__ int sh[1024];
    __shared__ int s_prev;
    int t = threadIdx.x, b = blockIdx.x;
    int i = b * 1024 + t;
    int v = (i < n) ? deg[i] : 0;
    sh[t] = v;
    __syncthreads();
    #pragma unroll
    for (int off = 1; off < 1024; off <<= 1) {
        int u = (t >= off) ? sh[t - off] : 0;
        __syncthreads();
        sh[t] += u;
        __syncthreads();
    }
    int total = sh[1023];

    if (t == 0) {
        if (b == 0) {
            prefv[0] = total;
            __threadfence();
            atomicExch(&flags[0], 2);
            s_prev = 0;
        } else {
            aggv[b] = total;
            __threadfence();
            atomicExch(&flags[b], 1);
            int prev = 0, j = b - 1;
            while (true) {
                int f;
                do { f = atomicAdd(&flags[j], 0); } while (f == 0);
                if (f == 2) { prev += prefv[j]; break; }
                prev += aggv[j];
                j--;
            }
            prefv[b] = prev + total;
            __threadfence();
            atomicExch(&flags[b], 2);
            s_prev = prev;
        }
    }
    __syncthreads();
    if (i < n) rowptr[i] = sh[t] - v + s_prev;
    if (i == 0) rowptr[n] = etot;
}

__global__ void k_scatter(const int* __restrict__ ei, const int* __restrict__ rowptr,
                          const int* __restrict__ offb, int* __restrict__ srcs,
                          int E, int ET) {
    int e = blockIdx.x * blockDim.x + threadIdx.x;
    if (e >= ET) return;
    int src, dst;
    if (e < E) { src = ei[e]; dst = ei[E + e]; }
    else       { src = dst = e - E; }
    srcs[rowptr[dst] + offb[e]] = src;
}

// ---------------- tensor-core dual GEMM ----------------
template <int K, bool XH>
__global__ void __launch_bounds__(256) k_gemm_tc(
        const void* __restrict__ Xv, const __half* __restrict__ WT,
        __half* __restrict__ xlh, float* __restrict__ xr, int N) {
    extern __shared__ __half smh[];
    const int KP = K + 8;
    __half* Ah = smh;              // [64][KP]
    __half* Bh = smh + 64 * KP;    // [128][KP]
    int tid = threadIdx.x;
    int base = blockIdx.x * 64;

    const int K8 = K / 8;
    if (XH) {
        const __half* Xh = (const __half*)Xv;
        for (int i = tid; i < 64 * K8; i += 256) {
            int r = i / K8, cb = (i % K8) * 8;
            int node = base + r;
            uint4 v = make_uint4(0, 0, 0, 0);
            if (node < N) v = *(const uint4*)&Xh[(size_t)node * K + cb];
            *(uint4*)&Ah[r * KP + cb] = v;
        }
    } else {
        const float* Xf = (const float*)Xv;
        const int K4 = K / 4;
        for (int i = tid; i < 64 * K4; i += 256) {
            int r = i / K4, cb = (i % K4) * 4;
            int node = base + r;
            float4 v = make_float4(0.f, 0.f, 0.f, 0.f);
            if (node < N) v = *(const float4*)&Xf[(size_t)node * K + cb];
            __half2 a = __floats2half2_rn(v.x, v.y);
            __half2 b = __floats2half2_rn(v.z, v.w);
            uint2 u;
            u.x = *(const unsigned*)&a;
            u.y = *(const unsigned*)&b;
            *(uint2*)&Ah[r * KP + cb] = u;
        }
    }
    for (int i = tid; i < 128 * K8; i += 256) {
        int n = i / K8, cb = (i % K8) * 8;
        *(uint4*)&Bh[n * KP + cb] = *(const uint4*)&WT[n * K + cb];
    }
    __syncthreads();

    int warp = tid >> 5, lane = tid & 31;
    int rw = (warp >> 2) * 32;
    int cw = (warp & 3) * 32;

    float acc[2][4][4];
    #pragma unroll
    for (int rt = 0; rt < 2; rt++)
        #pragma unroll
        for (int nt = 0; nt < 4; nt++)
            #pragma unroll
            for (int q = 0; q < 4; q++) acc[rt][nt][q] = 0.f;

    uint32_t a_smem = (uint32_t)__cvta_generic_to_shared(Ah);

    #pragma unroll
    for (int ks = 0; ks < K / 16; ks++) {
        int k0 = ks * 16;
        uint32_t afr[2][4];
        #pragma unroll
        for (int rt = 0; rt < 2; rt++) {
            int row = rw + rt * 16 + (lane & 15);
            int kc  = k0 + ((lane >> 4) << 3);
            uint32_t addr = a_smem + (row * KP + kc) * 2;
            asm volatile(
                "ldmatrix.sync.aligned.m8n8.x4.shared.b16 {%0,%1,%2,%3}, [%4];"
                : "=r"(afr[rt][0]), "=r"(afr[rt][1]),
                  "=r"(afr[rt][2]), "=r"(afr[rt][3])
                : "r"(addr));
        }
        #pragma unroll
        for (int nt = 0; nt < 4; nt++) {
            int n  = cw + nt * 8 + (lane >> 2);
            int kk = k0 + ((lane & 3) << 1);
            uint32_t b0 = *(const uint32_t*)&Bh[n * KP + kk];
            uint32_t b1 = *(const uint32_t*)&Bh[n * KP + kk + 8];
            #pragma unroll
            for (int rt = 0; rt < 2; rt++) {
                asm volatile(
                    "mma.sync.aligned.m16n8k16.row.col.f32.f16.f16.f32 "
                    "{%0,%1,%2,%3}, {%4,%5,%6,%7}, {%8,%9}, {%0,%1,%2,%3};"
                    : "+f"(acc[rt][nt][0]), "+f"(acc[rt][nt][1]),
                      "+f"(acc[rt][nt][2]), "+f"(acc[rt][nt][3])
                    : "r"(afr[rt][0]), "r"(afr[rt][1]),
                      "r"(afr[rt][2]), "r"(afr[rt][3]),
                      "r"(b0), "r"(b1));
            }
        }
    }

    int lr = lane >> 2, lc = (lane & 3) * 2;
    #pragma unroll
    for (int rt = 0; rt < 2; rt++) {
        #pragma unroll
        for (int h2 = 0; h2 < 2; h2++) {
            int node = base + rw + rt * 16 + lr + h2 * 8;
            if (node >= N) continue;
            #pragma unroll
            for (int nt = 0; nt < 4; nt++) {
                int col = cw + nt * 8 + lc;
                float v0 = acc[rt][nt][h2 * 2 + 0];
                float v1 = acc[rt][nt][h2 * 2 + 1];
                if (col < 64) {
                    *(__half2*)&xlh[(size_t)node * 64 + col] =
                        __floats2half2_rn(v0, v1);
                } else {
                    *(float2*)&xr[(size_t)node * 64 + (col - 64)] =
                        make_float2(v0, v1);
                }
            }
        }
    }
}

// ---------------- fused edge softmax + aggregation ----------------
// 2 warps per dst node (split edge range), 16 lanes per edge inside each warp.
// EDGE_PAIR internals identical to the proven R11 text (abs-trick).
template <bool HOUT>
__global__ void k_agg(const uint2* __restrict__ xlh4, const float* __restrict__ xr,
                      const int* __restrict__ rowptr, const int* __restrict__ srcs,
                      const float* __restrict__ att, const float* __restrict__ bias,
                      void* __restrict__ outp, int N) {
    __shared__ float red[8][16][5];   // per-warp partials: [warp][q][a0..a3,ps]

    int warp  = threadIdx.x >> 5;            // 0..7
    int lane  = threadIdx.x & 31;
    int nloc  = warp >> 1;                   // node slot in block: 0..3
    int whalf = warp & 1;                    // which half of edge range
    int node  = blockIdx.x * 4 + nloc;
    if (node >= N) return;

    int e2 = lane >> 4;
    int q  = lane & 15;
    const float4 xr4 = *(const float4*)&xr[(size_t)node * 64 + q * 4];
    const float4 at4 = ((const float4*)att)[q];
    float4 at6, atA;
    at6.x = 0.6f * at4.x; at6.y = 0.6f * at4.y;
    at6.z = 0.6f * at4.z; at6.w = 0.6f * at4.w;
    atA.x = 0.4f * at4.x; atA.y = 0.4f * at4.y;
    atA.z = 0.4f * at4.z; atA.w = 0.4f * at4.w;

    int n0 = rowptr[node], n1 = rowptr[node + 1];
    int mid = n0 + ((n1 - n0 + 1) >> 1);
    int e0 = whalf ? mid : n0;
    int e1 = whalf ? n1  : mid;

    float a0 = 0.f, a1 = 0.f, a2 = 0.f, a3 = 0.f, ps = 0.f;

    for (int base = e0; base < e1; base += 32) {
        int sv = srcs[min(base + lane, e1 - 1)];
        int cnt = min(32, e1 - base);
        int g = 0;

        #define EDGE_PAIR(G)                                                   \
        {                                                                      \
            int s = __shfl_sync(0xFFFFFFFFu, sv, (G) + e2);                    \
            uint2 u = xlh4[(size_t)s * 16 + q];                                \
            __half2 ha = *(const __half2*)&u.x;                                \
            __half2 hb = *(const __half2*)&u.y;                                \
            float2 va = __half22float2(ha);                                    \
            float2 vb = __half22float2(hb);                                    \
            float t0 = va.x + xr4.x, t1 = va.y + xr4.y;                        \
            float t2 = vb.x + xr4.z, t3 = vb.y + xr4.w;                        \
            float l = t0 * at6.x + fabsf(t0) * atA.x;                          \
            l += t1 * at6.y + fabsf(t1) * atA.y;                               \
            l += t2 * at6.z + fabsf(t2) * atA.z;                               \
            l += t3 * at6.w + fabsf(t3) * atA.w;                               \
            l += __shfl_xor_sync(0xFFFFFFFFu, l, 1);                           \
            l += __shfl_xor_sync(0xFFFFFFFFu, l, 2);                           \
            float p = __expf(l);                                               \
            ps += p;                                                           \
            a0 += va.x * p; a1 += va.y * p;                                    \
            a2 += vb.x * p; a3 += vb.y * p;                                    \
        }

        for (; g + 7 < cnt; g += 8) {
            EDGE_PAIR(g);
            EDGE_PAIR(g + 2);
            EDGE_PAIR(g + 4);
            EDGE_PAIR(g + 6);
        }
        for (; g + 3 < cnt; g += 4) {
            EDGE_PAIR(g);
            EDGE_PAIR(g + 2);
        }
        for (; g + 1 < cnt; g += 2) {
            EDGE_PAIR(g);
        }
        if (g < cnt) {
            int s = __shfl_sync(0xFFFFFFFFu, sv, g);
            uint2 u = xlh4[(size_t)s * 16 + q];
            __half2 ha = *(const __half2*)&u.x;
            __half2 hb = *(const __half2*)&u.y;
            float2 va = __half22float2(ha);
            float2 vb = __half22float2(hb);
            float t0 = va.x + xr4.x, t1 = va.y + xr4.y;
            float t2 = vb.x + xr4.z, t3 = vb.y + xr4.w;
            float l = t0 * at6.x + fabsf(t0) * atA.x;
            l += t1 * at6.y + fabsf(t1) * atA.y;
            l += t2 * at6.z + fabsf(t2) * atA.z;
            l += t3 * at6.w + fabsf(t3) * atA.w;
            l += __shfl_xor_sync(0xFFFFFFFFu, l, 1);
            l += __shfl_xor_sync(0xFFFFFFFFu, l, 2);
            float p = (e2 == 0) ? __expf(l) : 0.f;
            ps += p;
            a0 += va.x * p; a1 += va.y * p;
            a2 += vb.x * p; a3 += vb.y * p;
        }
        #undef EDGE_PAIR
    }

    // combine the two edge-halves within the warp
    a0 += __shfl_xor_sync(0xFFFFFFFFu, a0, 16);
    a1 += __shfl_xor_sync(0xFFFFFFFFu, a1, 16);
    a2 += __shfl_xor_sync(0xFFFFFFFFu, a2, 16);
    a3 += __shfl_xor_sync(0xFFFFFFFFu, a3, 16);
    ps += __shfl_xor_sync(0xFFFFFFFFu, ps, 16);

    // cross-warp combine via smem
    if (e2 == 0) {
        red[warp][q][0] = a0;
        red[warp][q][1] = a1;
        red[warp][q][2] = a2;
        red[warp][q][3] = a3;
        red[warp][q][4] = ps;
    }
    __syncthreads();

    if (whalf == 0 && e2 == 0) {
        a0 += red[warp + 1][q][0];
        a1 += red[warp + 1][q][1];
        a2 += red[warp + 1][q][2];
        a3 += red[warp + 1][q][3];
        ps += red[warp + 1][q][4];

        const float4 b4 = *(const float4*)&bias[q * 4];
        float inv = 1.f / ps;
        float o0 = fmaxf(a0 * inv + b4.x, 0.f);
        float o1 = fmaxf(a1 * inv + b4.y, 0.f);
        float o2 = fmaxf(a2 * inv + b4.z, 0.f);
        float o3 = fmaxf(a3 * inv + b4.w, 0.f);
        if (HOUT) {
            __half2 ha = __floats2half2_rn(o0, o1);
            __half2 hb = __floats2half2_rn(o2, o3);
            uint2 u;
            u.x = *(const unsigned*)&ha;
            u.y = *(const unsigned*)&hb;
            ((uint2*)outp)[(size_t)node * 16 + q] = u;
        } else {
            float4 o = make_float4(o0, o1, o2, o3);
            ((float4*)outp)[(size_t)node * 16 + q] = o;
        }
    }
}

// ---------------- launch ----------------
extern "C" void kernel_launch(void* const* d_in, const int* in_sizes, int n_in,
                              void* d_out, int out_size) {
    const float* x    = (const float*)d_in[0];
    const int*   ei   = (const int*)  d_in[1];
    const float* W1l  = (const float*)d_in[2];
    const float* W1r  = (const float*)d_in[3];
    const float* att1 = (const float*)d_in[4];
    const float* b1   = (const float*)d_in[5];
    const float* W2l  = (const float*)d_in[6];
    const float* W2r  = (const float*)d_in[7];
    const float* att2 = (const float*)d_in[8];
    const float* b2   = (const float*)d_in[9];

    int F  = in_sizes[2] / D_OUT;     // 128
    int N  = in_sizes[0] / F;         // 100000
    int E  = in_sizes[1] / 2;         // 1600000
    int ET = E + N;
    if (N > MAXN || ET > MAXE || F != 128) return;

    void *p_hh, *p_xlh, *p_xr, *p_wt1, *p_wt2;
    void *p_deg, *p_rp, *p_src, *p_off, *p_fl, *p_ag, *p_pf;
    cudaGetSymbolAddress(&p_hh,  g_hh);
    cudaGetSymbolAddress(&p_xlh, g_xlh);
    cudaGetSymbolAddress(&p_xr,  g_xr);
    cudaGetSymbolAddress(&p_wt1, g_wt1);
    cudaGetSymbolAddress(&p_wt2, g_wt2);
    cudaGetSymbolAddress(&p_deg, g_deg);
    cudaGetSymbolAddress(&p_rp,  g_rowptr);
    cudaGetSymbolAddress(&p_src, g_srcs);
    cudaGetSymbolAddress(&p_off, g_off);
    cudaGetSymbolAddress(&p_fl,  g_flags);
    cudaGetSymbolAddress(&p_ag,  g_aggv);
    cudaGetSymbolAddress(&p_pf,  g_prefv);

    __half* hh  = (__half*)p_hh;
    __half* xlh = (__half*)p_xlh;
    float*  xr  = (float*)p_xr;
    __half* wt1 = (__half*)p_wt1;
    __half* wt2 = (__half*)p_wt2;
    int* deg    = (int*)p_deg;
    int* rp     = (int*)p_rp;
    int* srcs   = (int*)p_src;
    int* offb   = (int*)p_off;
    int* flags  = (int*)p_fl;
    int* aggv   = (int*)p_ag;
    int* prefv  = (int*)p_pf;

    size_t smem128 = (size_t)192 * 136 * 2;  // 52224 B
    size_t smem64  = (size_t)192 * 72  * 2;  // 27648 B
    cudaFuncSetAttribute((const void*)k_gemm_tc<128, false>,
                         cudaFuncAttributeMaxDynamicSharedMemorySize, (int)smem128);
    cudaFuncSetAttribute((const void*)k_gemm_tc<64, true>,
                         cudaFuncAttributeMaxDynamicSharedMemorySize, (int)smem64);

    // one-time side streams + events (created on the first, non-captured call)
    static cudaStream_t s1 = nullptr, s2 = nullptr;
    static cudaEvent_t evFork = nullptr, evCSR = nullptr, evGEMM = nullptr;
    if (s1 == nullptr) {
        cudaStreamCreateWithFlags(&s1, cudaStreamNonBlocking);
        cudaStreamCreateWithFlags(&s2, cudaStreamNonBlocking);
        cudaEventCreateWithFlags(&evFork, cudaEventDisableTiming);
        cudaEventCreateWithFlags(&evCSR,  cudaEventDisableTiming);
        cudaEventCreateWithFlags(&evGEMM, cudaEventDisableTiming);
    }

    int NB = (N + 1023) / 1024;
    int nbE = (ET + 255) / 256;
    int zeroBlocks = (N + 255) / 256;
    int wcvtBlocks = (128 * 128 + 255) / 256;
    int gemmBlocks = (N + 63) / 64;
    int aggBlocks  = (N + 3) / 4;

    // fork: both chains on non-legacy streams so they can truly overlap
    cudaEventRecord(evFork, 0);
    cudaStreamWaitEvent(s1, evFork, 0);
    cudaStreamWaitEvent(s2, evFork, 0);

    // s1: CSR chain
    k_zerodeg<<<zeroBlocks, 256, 0, s1>>>(deg, flags, N, NB);
    k_count<<<nbE, 256, 0, s1>>>(ei, deg, offb, E, ET);
    k_scan<<<NB, 1024, 0, s1>>>(deg, rp, flags, aggv, prefv, N, ET);
    k_scatter<<<nbE, 256, 0, s1>>>(ei, rp, offb, srcs, E, ET);
    cudaEventRecord(evCSR, s1);

    // s2: W transpose + layer-1 GEMM
    k_wcvt<<<wcvtBlocks, 256, 0, s2>>>(W1l, W1r, W2l, W2r, wt1, wt2);
    k_gemm_tc<128, false><<<gemmBlocks, 256, smem128, s2>>>(x, wt1, xlh, xr, N);
    cudaEventRecord(evGEMM, s2);

    // join on legacy stream: agg needs both
    cudaStreamWaitEvent(0, evCSR, 0);
    cudaStreamWaitEvent(0, evGEMM, 0);
    k_agg<true><<<aggBlocks, 256>>>((const uint2*)xlh, xr, rp, srcs,
                                    att1, b1, (void*)hh, N);
    k_gemm_tc<64, true><<<gemmBlocks, 256, smem64>>>(hh, wt2, xlh, xr, N);
    k_agg<false><<<aggBlocks, 256>>>((const uint2*)xlh, xr, rp, srcs,
                                     att2, b2, (void*)d_out, N);
}

// round 14
// speedup vs baseline: 1.2592x; 1.2592x over previous
#include <cuda_runtime.h>
#include <cuda_fp16.h>
#include <cstdint>

#define MAXN 100352
#define MAXE 1703936
#define D_OUT 64
#define MAXNB 128

// ---------------- scratch ----------------
__device__ __half g_hh [(size_t)MAXN * D_OUT];   // fp16 layer-1 output
__device__ __half g_xlh[(size_t)MAXN * D_OUT];   // fp16 gather array
__device__ float  g_xr[(size_t)MAXN * D_OUT];
__device__ __half g_wt1[128 * 128];              // (W1l|W1r)^T fp16 [n][k]
__device__ __half g_wt2[128 * 64];               // (W2l|W2r)^T fp16 [n][k]
__device__ int    g_deg[MAXN];
__device__ int    g_rowptr[MAXN + 1];
__device__ int    g_srcs[MAXE];
__device__ int    g_off[MAXE];
__device__ int    g_flags[MAXNB];
__device__ int    g_aggv [MAXNB];
__device__ int    g_prefv[MAXNB];

// ---------------- W fp16 transpose ----------------
__global__ void k_wcvt(const float* __restrict__ W1l, const float* __restrict__ W1r,
                       const float* __restrict__ W2l, const float* __restrict__ W2r,
                       __half* __restrict__ wt1, __half* __restrict__ wt2) {
    int i = blockIdx.x * 256 + threadIdx.x;
    if (i < 128 * 128) {
        int nn = i >> 7, k = i & 127;
        float w = (nn < 64) ? W1l[k * 64 + nn] : W1r[k * 64 + (nn - 64)];
        wt1[i] = __float2half(w);
    }
    if (i < 128 * 64) {
        int nn = i >> 6, k = i & 63;
        float w = (nn < 64) ? W2l[k * 64 + nn] : W2r[k * 64 + (nn - 64)];
        wt2[i] = __float2half(w);
    }
}

__global__ void k_zerodeg(int* __restrict__ deg, int* __restrict__ flags,
                          int n, int nb) {
    int i = blockIdx.x * 256 + threadIdx.x;
    if (i < n) deg[i] = 0;
    if (i < nb) flags[i] = 0;
}

// ---------------- CSR build ----------------
__global__ void k_count(const int* __restrict__ ei, int* __restrict__ deg,
                        int* __restrict__ offb, int E, int ET) {
    int e = blockIdx.x * blockDim.x + threadIdx.x;
    if (e >= ET) return;
    int dst = (e < E) ? ei[E + e] : (e - E);
    offb[e] = atomicAdd(&deg[dst], 1);
}

__global__ void k_scan(const int* __restrict__ deg, int* __restrict__ rowptr,
                       int* __restrict__ flags,
                       int* __restrict__ aggv, int* __restrict__ prefv,
                       int n, int etot) {
    __shared__ int sh[1024];
    __shared__ int s_prev;
    int t = threadIdx.x, b = blockIdx.x;
    int i = b * 1024 + t;
    int v = (i < n) ? deg[i] : 0;
    sh[t] = v;
    __syncthreads();
    #pragma unroll
    for (int off = 1; off < 1024; off <<= 1) {
        int u = (t >= off) ? sh[t - off] : 0;
        __syncthreads();
        sh[t] += u;
        __syncthreads();
    }
    int total = sh[1023];

    if (t == 0) {
        if (b == 0) {
            prefv[0] = total;
            __threadfence();
            atomicExch(&flags[0], 2);
            s_prev = 0;
        } else {
            aggv[b] = total;
            __threadfence();
            atomicExch(&flags[b], 1);
            int prev = 0, j = b - 1;
            while (true) {
                int f;
                do { f = atomicAdd(&flags[j], 0); } while (f == 0);
                if (f == 2) { prev += prefv[j]; break; }
                prev += aggv[j];
                j--;
            }
            prefv[b] = prev + total;
            __threadfence();
            atomicExch(&flags[b], 2);
            s_prev = prev;
        }
    }
    __syncthreads();
    if (i < n) rowptr[i] = sh[t] - v + s_prev;
    if (i == 0) rowptr[n] = etot;
}

__global__ void k_scatter(const int* __restrict__ ei, const int* __restrict__ rowptr,
                          const int* __restrict__ offb, int* __restrict__ srcs,
                          int E, int ET) {
    int e = blockIdx.x * blockDim.x + threadIdx.x;
    if (e >= ET) return;
    int src, dst;
    if (e < E) { src = ei[e]; dst = ei[E + e]; }
    else       { src = dst = e - E; }
    srcs[rowptr[dst] + offb[e]] = src;
}

// ---------------- tensor-core dual GEMM ----------------
template <int K, bool XH>
__global__ void __launch_bounds__(256) k_gemm_tc(
        const void* __restrict__ Xv, const __half* __restrict__ WT,
        __half* __restrict__ xlh, float* __restrict__ xr, int N) {
    extern __shared__ __half smh[];
    const int KP = K + 8;
    __half* Ah = smh;              // [64][KP]
    __half* Bh = smh + 64 * KP;    // [128][KP]
    int tid = threadIdx.x;
    int base = blockIdx.x * 64;

    const int K8 = K / 8;
    if (XH) {
        const __half* Xh = (const __half*)Xv;
        for (int i = tid; i < 64 * K8; i += 256) {
            int r = i / K8, cb = (i % K8) * 8;
            int node = base + r;
            uint4 v = make_uint4(0, 0, 0, 0);
            if (node < N) v = *(const uint4*)&Xh[(size_t)node * K + cb];
            *(uint4*)&Ah[r * KP + cb] = v;
        }
    } else {
        const float* Xf = (const float*)Xv;
        const int K4 = K / 4;
        for (int i = tid; i < 64 * K4; i += 256) {
            int r = i / K4, cb = (i % K4) * 4;
            int node = base + r;
            float4 v = make_float4(0.f, 0.f, 0.f, 0.f);
            if (node < N) v = *(const float4*)&Xf[(size_t)node * K + cb];
            __half2 a = __floats2half2_rn(v.x, v.y);
            __half2 b = __floats2half2_rn(v.z, v.w);
            uint2 u;
            u.x = *(const unsigned*)&a;
            u.y = *(const unsigned*)&b;
            *(uint2*)&Ah[r * KP + cb] = u;
        }
    }
    for (int i = tid; i < 128 * K8; i += 256) {
        int n = i / K8, cb = (i % K8) * 8;
        *(uint4*)&Bh[n * KP + cb] = *(const uint4*)&WT[n * K + cb];
    }
    __syncthreads();

    int warp = tid >> 5, lane = tid & 31;
    int rw = (warp >> 2) * 32;
    int cw = (warp & 3) * 32;

    float acc[2][4][4];
    #pragma unroll
    for (int rt = 0; rt < 2; rt++)
        #pragma unroll
        for (int nt = 0; nt < 4; nt++)
            #pragma unroll
            for (int q = 0; q < 4; q++) acc[rt][nt][q] = 0.f;

    uint32_t a_smem = (uint32_t)__cvta_generic_to_shared(Ah);

    #pragma unroll
    for (int ks = 0; ks < K / 16; ks++) {
        int k0 = ks * 16;
        uint32_t afr[2][4];
        #pragma unroll
        for (int rt = 0; rt < 2; rt++) {
            int row = rw + rt * 16 + (lane & 15);
            int kc  = k0 + ((lane >> 4) << 3);
            uint32_t addr = a_smem + (row * KP + kc) * 2;
            asm volatile(
                "ldmatrix.sync.aligned.m8n8.x4.shared.b16 {%0,%1,%2,%3}, [%4];"
                : "=r"(afr[rt][0]), "=r"(afr[rt][1]),
                  "=r"(afr[rt][2]), "=r"(afr[rt][3])
                : "r"(addr));
        }
        #pragma unroll
        for (int nt = 0; nt < 4; nt++) {
            int n  = cw + nt * 8 + (lane >> 2);
            int kk = k0 + ((lane & 3) << 1);
            uint32_t b0 = *(const uint32_t*)&Bh[n * KP + kk];
            uint32_t b1 = *(const uint32_t*)&Bh[n * KP + kk + 8];
            #pragma unroll
            for (int rt = 0; rt < 2; rt++) {
                asm volatile(
                    "mma.sync.aligned.m16n8k16.row.col.f32.f16.f16.f32 "
                    "{%0,%1,%2,%3}, {%4,%5,%6,%7}, {%8,%9}, {%0,%1,%2,%3};"
                    : "+f"(acc[rt][nt][0]), "+f"(acc[rt][nt][1]),
                      "+f"(acc[rt][nt][2]), "+f"(acc[rt][nt][3])
                    : "r"(afr[rt][0]), "r"(afr[rt][1]),
                      "r"(afr[rt][2]), "r"(afr[rt][3]),
                      "r"(b0), "r"(b1));
            }
        }
    }

    int lr = lane >> 2, lc = (lane & 3) * 2;
    #pragma unroll
    for (int rt = 0; rt < 2; rt++) {
        #pragma unroll
        for (int h2 = 0; h2 < 2; h2++) {
            int node = base + rw + rt * 16 + lr + h2 * 8;
            if (node >= N) continue;
            #pragma unroll
            for (int nt = 0; nt < 4; nt++) {
                int col = cw + nt * 8 + lc;
                float v0 = acc[rt][nt][h2 * 2 + 0];
                float v1 = acc[rt][nt][h2 * 2 + 1];
                if (col < 64) {
                    *(__half2*)&xlh[(size_t)node * 64 + col] =
                        __floats2half2_rn(v0, v1);
                } else {
                    *(float2*)&xr[(size_t)node * 64 + (col - 64)] =
                        make_float2(v0, v1);
                }
            }
        }
    }
}

// ---------------- fused edge softmax + aggregation ----------------
// warp per dst node (R12 text), launched with 64-thread blocks to cut
// degree-imbalance tail (block waits on max-of-2 degrees, not max-of-8).
template <bool HOUT>
__global__ void k_agg(const uint2* __restrict__ xlh4, const float* __restrict__ xr,
                      const int* __restrict__ rowptr, const int* __restrict__ srcs,
                      const float* __restrict__ att, const float* __restrict__ bias,
                      void* __restrict__ outp, int N) {
    int node = (blockIdx.x * blockDim.x + threadIdx.x) >> 5;
    int lane = threadIdx.x & 31;
    if (node >= N) return;

    int e2 = lane >> 4;
    int q  = lane & 15;
    const float4 xr4 = *(const float4*)&xr[(size_t)node * 64 + q * 4];
    const float4 at4 = ((const float4*)att)[q];
    float4 at6, atA;
    at6.x = 0.6f * at4.x; at6.y = 0.6f * at4.y;
    at6.z = 0.6f * at4.z; at6.w = 0.6f * at4.w;
    atA.x = 0.4f * at4.x; atA.y = 0.4f * at4.y;
    atA.z = 0.4f * at4.z; atA.w = 0.4f * at4.w;

    int e0 = rowptr[node], e1 = rowptr[node + 1];
    float a0 = 0.f, a1 = 0.f, a2 = 0.f, a3 = 0.f, ps = 0.f;

    for (int base = e0; base < e1; base += 32) {
        int sv = srcs[min(base + lane, e1 - 1)];
        int cnt = min(32, e1 - base);
        int g = 0;

        #define EDGE_PAIR(G)                                                   \
        {                                                                      \
            int s = __shfl_sync(0xFFFFFFFFu, sv, (G) + e2);                    \
            uint2 u = xlh4[(size_t)s * 16 + q];                                \
            __half2 ha = *(const __half2*)&u.x;                                \
            __half2 hb = *(const __half2*)&u.y;                                \
            float2 va = __half22float2(ha);                                    \
            float2 vb = __half22float2(hb);                                    \
            float t0 = va.x + xr4.x, t1 = va.y + xr4.y;                        \
            float t2 = vb.x + xr4.z, t3 = vb.y + xr4.w;                        \
            float l = t0 * at6.x + fabsf(t0) * atA.x;                          \
            l += t1 * at6.y + fabsf(t1) * atA.y;                               \
            l += t2 * at6.z + fabsf(t2) * atA.z;                               \
            l += t3 * at6.w + fabsf(t3) * atA.w;                               \
            l += __shfl_xor_sync(0xFFFFFFFFu, l, 1);                           \
            l += __shfl_xor_sync(0xFFFFFFFFu, l, 2);                           \
            float p = __expf(l);                                               \
            ps += p;                                                           \
            a0 += va.x * p; a1 += va.y * p;                                    \
            a2 += vb.x * p; a3 += vb.y * p;                                    \
        }

        for (; g + 7 < cnt; g += 8) {
            EDGE_PAIR(g);
            EDGE_PAIR(g + 2);
            EDGE_PAIR(g + 4);
            EDGE_PAIR(g + 6);
        }
        for (; g + 3 < cnt; g += 4) {
            EDGE_PAIR(g);
            EDGE_PAIR(g + 2);
        }
        for (; g + 1 < cnt; g += 2) {
            EDGE_PAIR(g);
        }
        if (g < cnt) {
            int s = __shfl_sync(0xFFFFFFFFu, sv, g);
            uint2 u = xlh4[(size_t)s * 16 + q];
            __half2 ha = *(const __half2*)&u.x;
            __half2 hb = *(const __half2*)&u.y;
            float2 va = __half22float2(ha);
            float2 vb = __half22float2(hb);
            float t0 = va.x + xr4.x, t1 = va.y + xr4.y;
            float t2 = vb.x + xr4.z, t3 = vb.y + xr4.w;
            float l = t0 * at6.x + fabsf(t0) * atA.x;
            l += t1 * at6.y + fabsf(t1) * atA.y;
            l += t2 * at6.z + fabsf(t2) * atA.z;
            l += t3 * at6.w + fabsf(t3) * atA.w;
            l += __shfl_xor_sync(0xFFFFFFFFu, l, 1);
            l += __shfl_xor_sync(0xFFFFFFFFu, l, 2);
            float p = (e2 == 0) ? __expf(l) : 0.f;
            ps += p;
            a0 += va.x * p; a1 += va.y * p;
            a2 += vb.x * p; a3 += vb.y * p;
        }
        #undef EDGE_PAIR
    }

    a0 += __shfl_xor_sync(0xFFFFFFFFu, a0, 16);
    a1 += __shfl_xor_sync(0xFFFFFFFFu, a1, 16);
    a2 += __shfl_xor_sync(0xFFFFFFFFu, a2, 16);
    a3 += __shfl_xor_sync(0xFFFFFFFFu, a3, 16);
    ps += __shfl_xor_sync(0xFFFFFFFFu, ps, 16);

    if (e2 == 0) {
        const float4 b4 = *(const float4*)&bias[q * 4];
        float inv = 1.f / ps;
        float o0 = fmaxf(a0 * inv + b4.x, 0.f);
        float o1 = fmaxf(a1 * inv + b4.y, 0.f);
        float o2 = fmaxf(a2 * inv + b4.z, 0.f);
        float o3 = fmaxf(a3 * inv + b4.w, 0.f);
        if (HOUT) {
            __half2 ha = __floats2half2_rn(o0, o1);
            __half2 hb = __floats2half2_rn(o2, o3);
            uint2 u;
            u.x = *(const unsigned*)&ha;
            u.y = *(const unsigned*)&hb;
            ((uint2*)outp)[(size_t)node * 16 + q] = u;
        } else {
            float4 o = make_float4(o0, o1, o2, o3);
            ((float4*)outp)[(size_t)node * 16 + q] = o;
        }
    }
}

// ---------------- launch ----------------
extern "C" void kernel_launch(void* const* d_in, const int* in_sizes, int n_in,
                              void* d_out, int out_size) {
    const float* x    = (const float*)d_in[0];
    const int*   ei   = (const int*)  d_in[1];
    const float* W1l  = (const float*)d_in[2];
    const float* W1r  = (const float*)d_in[3];
    const float* att1 = (const float*)d_in[4];
    const float* b1   = (const float*)d_in[5];
    const float* W2l  = (const float*)d_in[6];
    const float* W2r  = (const float*)d_in[7];
    const float* att2 = (const float*)d_in[8];
    const float* b2   = (const float*)d_in[9];

    int F  = in_sizes[2] / D_OUT;     // 128
    int N  = in_sizes[0] / F;         // 100000
    int E  = in_sizes[1] / 2;         // 1600000
    int ET = E + N;
    if (N > MAXN || ET > MAXE || F != 128) return;

    void *p_hh, *p_xlh, *p_xr, *p_wt1, *p_wt2;
    void *p_deg, *p_rp, *p_src, *p_off, *p_fl, *p_ag, *p_pf;
    cudaGetSymbolAddress(&p_hh,  g_hh);
    cudaGetSymbolAddress(&p_xlh, g_xlh);
    cudaGetSymbolAddress(&p_xr,  g_xr);
    cudaGetSymbolAddress(&p_wt1, g_wt1);
    cudaGetSymbolAddress(&p_wt2, g_wt2);
    cudaGetSymbolAddress(&p_deg, g_deg);
    cudaGetSymbolAddress(&p_rp,  g_rowptr);
    cudaGetSymbolAddress(&p_src, g_srcs);
    cudaGetSymbolAddress(&p_off, g_off);
    cudaGetSymbolAddress(&p_fl,  g_flags);
    cudaGetSymbolAddress(&p_ag,  g_aggv);
    cudaGetSymbolAddress(&p_pf,  g_prefv);

    __half* hh  = (__half*)p_hh;
    __half* xlh = (__half*)p_xlh;
    float*  xr  = (float*)p_xr;
    __half* wt1 = (__half*)p_wt1;
    __half* wt2 = (__half*)p_wt2;
    int* deg    = (int*)p_deg;
    int* rp     = (int*)p_rp;
    int* srcs   = (int*)p_src;
    int* offb   = (int*)p_off;
    int* flags  = (int*)p_fl;
    int* aggv   = (int*)p_ag;
    int* prefv  = (int*)p_pf;

    size_t smem128 = (size_t)192 * 136 * 2;  // 52224 B
    size_t smem64  = (size_t)192 * 72  * 2;  // 27648 B
    cudaFuncSetAttribute((const void*)k_gemm_tc<128, false>,
                         cudaFuncAttributeMaxDynamicSharedMemorySize, (int)smem128);
    cudaFuncSetAttribute((const void*)k_gemm_tc<64, true>,
                         cudaFuncAttributeMaxDynamicSharedMemorySize, (int)smem64);

    // one-time side streams + events (created on the first, non-captured call)
    static cudaStream_t s1 = nullptr, s2 = nullptr;
    static cudaEvent_t evFork = nullptr, evCSR = nullptr, evGEMM = nullptr;
    if (s1 == nullptr) {
        cudaStreamCreateWithFlags(&s1, cudaStreamNonBlocking);
        cudaStreamCreateWithFlags(&s2, cudaStreamNonBlocking);
        cudaEventCreateWithFlags(&evFork, cudaEventDisableTiming);
        cudaEventCreateWithFlags(&evCSR,  cudaEventDisableTiming);
        cudaEventCreateWithFlags(&evGEMM, cudaEventDisableTiming);
    }

    int NB = (N + 1023) / 1024;
    int nbE = (ET + 255) / 256;
    int zeroBlocks = (N + 255) / 256;
    int wcvtBlocks = (128 * 128 + 255) / 256;
    int gemmBlocks = (N + 63) / 64;
    int aggBlocks  = (N + 1) / 2;      // 64-thread blocks, warp per node

    // fork: both chains on non-legacy streams so they truly overlap
    cudaEventRecord(evFork, 0);
    cudaStreamWaitEvent(s1, evFork, 0);
    cudaStreamWaitEvent(s2, evFork, 0);

    // s1: CSR chain
    k_zerodeg<<<zeroBlocks, 256, 0, s1>>>(deg, flags, N, NB);
    k_count<<<nbE, 256, 0, s1>>>(ei, deg, offb, E, ET);
    k_scan<<<NB, 1024, 0, s1>>>(deg, rp, flags, aggv, prefv, N, ET);
    k_scatter<<<nbE, 256, 0, s1>>>(ei, rp, offb, srcs, E, ET);
    cudaEventRecord(evCSR, s1);

    // s2: W transpose + layer-1 GEMM
    k_wcvt<<<wcvtBlocks, 256, 0, s2>>>(W1l, W1r, W2l, W2r, wt1, wt2);
    k_gemm_tc<128, false><<<gemmBlocks, 256, smem128, s2>>>(x, wt1, xlh, xr, N);
    cudaEventRecord(evGEMM, s2);

    // join on legacy stream: agg needs both
    cudaStreamWaitEvent(0, evCSR, 0);
    cudaStreamWaitEvent(0, evGEMM, 0);
    k_agg<true><<<aggBlocks, 64>>>((const uint2*)xlh, xr, rp, srcs,
                                   att1, b1, (void*)hh, N);
    k_gemm_tc<64, true><<<gemmBlocks, 256, smem64>>>(hh, wt2, xlh, xr, N);
    k_agg<false><<<aggBlocks, 64>>>((const uint2*)xlh, xr, rp, srcs,
                                    att2, b2, (void*)d_out, N);
}